// round 8
// baseline (speedup 1.0000x reference)
#include <cuda_runtime.h>
#include <math.h>

// ---------------- problem constants ----------------
#define BB   2
#define SS   1024
#define TT   1024
#define HH   2048
#define NHH  16
#define HDD  128
#define MTOK 2048

// ---------------- device scratch ----------------
__device__ float g_ln    [2048u * 2048];   // A-packed
__device__ float g_qkv   [2048u * 6144];   // row-major (flash input)
__device__ float g_ctx   [2048u * 2048];   // A-packed (flash output)
__device__ float g_x     [2048u * 2048];   // row-major
__device__ float g_q     [2048u * 2048];   // row-major (flash input)
__device__ float g_kv    [2048u * 4096];   // row-major (flash input)
__device__ float g_mlp   [2048u * 8192];   // A-packed
__device__ float g_enc   [2048u * 2048];   // A-packed
__device__ float g_w     [67108864];       // B-fragment-packed weights

// ---------------- helpers ----------------
__device__ __forceinline__ unsigned f2tf(float x) {
    unsigned u; asm("cvt.rna.tf32.f32 %0, %1;" : "=r"(u) : "f"(x)); return u;
}
__device__ __forceinline__ float rtf(float x) { return __uint_as_float(f2tf(x)); }
// XOR-swizzled [row][32] word layout (flash tiles only)
__device__ __forceinline__ int aswz(int m, int k) {
    return m * 32 + (((((k) >> 2) ^ (m & 7)) << 2) | (k & 3));
}
__device__ __forceinline__ void mma8(float* c, const unsigned* a, const unsigned* b) {
    asm volatile(
        "mma.sync.aligned.m16n8k8.row.col.f32.tf32.tf32.f32 "
        "{%0,%1,%2,%3}, {%4,%5,%6,%7}, {%8,%9}, {%0,%1,%2,%3};"
        : "+f"(c[0]), "+f"(c[1]), "+f"(c[2]), "+f"(c[3])
        : "r"(a[0]), "r"(a[1]), "r"(a[2]), "r"(a[3]), "r"(b[0]), "r"(b[1]));
}
__device__ __forceinline__ float gelu_f(float u) {
    return 0.5f * u * (1.f + tanhf(0.7978845608028654f * u * (1.f + 0.044715f * u * u)));
}

// ---------------- reductions ----------------
__device__ __forceinline__ float blockReduceSum(float v, float* sh) {
    int lane = threadIdx.x & 31, w = threadIdx.x >> 5;
    #pragma unroll
    for (int o = 16; o > 0; o >>= 1) v += __shfl_xor_sync(0xffffffffu, v, o);
    if (lane == 0) sh[w] = v;
    __syncthreads();
    float r = 0.f;
    if (w == 0) {
        r = (lane < (blockDim.x >> 5)) ? sh[lane] : 0.f;
        #pragma unroll
        for (int o = 16; o > 0; o >>= 1) r += __shfl_xor_sync(0xffffffffu, r, o);
        if (lane == 0) sh[0] = r;
    }
    __syncthreads();
    r = sh[0];
    __syncthreads();
    return r;
}

// =========================================================================
// Packing layouts
//  A-pack (activations, M=2048 rows): A'[(k>>3)*16384 + m*8 + t],
//    t = (k&3)*2 + ((k>>2)&1)   (i.e. word pair (t,t+1) => k, k+4 for t even)
//  B-pack (weights): B'[(k>>3)*N*8 + n*8 + t], same t mapping (R5 layout)
// =========================================================================

// weight pack: W[K][N] row-major -> B-frag pack (with tf32 rounding)
__global__ void __launch_bounds__(256) packw_kernel(const float* __restrict__ W,
                                                    float* __restrict__ P,
                                                    int K, int N) {
    int nb = (K >> 3) * N;   // 8-word groups
    for (int g = blockIdx.x * blockDim.x + threadIdx.x; g < nb;
         g += gridDim.x * blockDim.x) {
        int kb = g / N;
        int n = g - kb * N;
        const float* src = W + (size_t)(kb * 8) * N + n;
        float* d = P + (size_t)kb * N * 8 + n * 8;
        // t -> k = (t>>1) + ((t&1)<<2)
        d[0] = rtf(src[0]);
        d[1] = rtf(src[4 * (size_t)N]);
        d[2] = rtf(src[(size_t)N]);
        d[3] = rtf(src[5 * (size_t)N]);
        d[4] = rtf(src[2 * (size_t)N]);
        d[5] = rtf(src[6 * (size_t)N]);
        d[6] = rtf(src[3 * (size_t)N]);
        d[7] = rtf(src[7 * (size_t)N]);
    }
}

// activation pack: src[M=2048][K] row-major -> A-pack (tf32 rounded)
__global__ void __launch_bounds__(256) packa_kernel(const float* __restrict__ src,
                                                    float* __restrict__ dst, int K) {
    int ngrp = (K >> 3) * MTOK;
    for (int i = blockIdx.x * blockDim.x + threadIdx.x; i < ngrp;
         i += gridDim.x * blockDim.x) {
        int m = i & (MTOK - 1);
        int kb = i >> 11;
        const float* s = src + (size_t)m * K + kb * 8;
        float4 o0, o1;
        o0.x = rtf(s[0]); o0.y = rtf(s[4]); o0.z = rtf(s[1]); o0.w = rtf(s[5]);
        o1.x = rtf(s[2]); o1.y = rtf(s[6]); o1.z = rtf(s[3]); o1.w = rtf(s[7]);
        float4* d = (float4*)(dst + ((size_t)kb << 14) + m * 8);
        d[0] = o0; d[1] = o1;
    }
}

// ---------------- layernorm: row-major in -> A-packed tf32 out ----------------
__global__ void __launch_bounds__(256) ln_kernel(const float* __restrict__ x,
                                                 const float* __restrict__ gw,
                                                 const float* __restrict__ gb,
                                                 float* __restrict__ out) {
    __shared__ float sh[32];
    size_t base = (size_t)blockIdx.x * HH;
    int tid = threadIdx.x;
    float4 a = *(const float4*)(x + base + tid * 4);
    float4 b = *(const float4*)(x + base + 1024 + tid * 4);
    float s = a.x + a.y + a.z + a.w + b.x + b.y + b.z + b.w;
    s = blockReduceSum(s, sh);
    float mean = s * (1.f / HH);
    float d, sq = 0.f;
    d = a.x - mean; sq += d * d; d = a.y - mean; sq += d * d;
    d = a.z - mean; sq += d * d; d = a.w - mean; sq += d * d;
    d = b.x - mean; sq += d * d; d = b.y - mean; sq += d * d;
    d = b.z - mean; sq += d * d; d = b.w - mean; sq += d * d;
    sq = blockReduceSum(sq, sh);
    float rstd = rsqrtf(sq * (1.f / HH) + 1e-5f);
    float4 g0 = *(const float4*)(gw + tid * 4);
    float4 g1 = *(const float4*)(gw + 1024 + tid * 4);
    float4 b0 = *(const float4*)(gb + tid * 4);
    float4 b1 = *(const float4*)(gb + 1024 + tid * 4);
    // packed write: col k = tid*4 + i -> group (tid>>1), word i*2 + (tid&1)
    int bsel = tid & 1;
    float* p0 = out + ((size_t)(tid >> 1) << 14) + (size_t)blockIdx.x * 8 + bsel;
    p0[0] = rtf((a.x - mean) * rstd * g0.x + b0.x);
    p0[2] = rtf((a.y - mean) * rstd * g0.y + b0.y);
    p0[4] = rtf((a.z - mean) * rstd * g0.z + b0.z);
    p0[6] = rtf((a.w - mean) * rstd * g0.w + b0.w);
    float* p1 = out + ((size_t)(128 + (tid >> 1)) << 14) + (size_t)blockIdx.x * 8 + bsel;
    p1[0] = rtf((b.x - mean) * rstd * g1.x + b1.x);
    p1[2] = rtf((b.y - mean) * rstd * g1.y + b1.y);
    p1[4] = rtf((b.z - mean) * rstd * g1.z + b1.z);
    p1[6] = rtf((b.w - mean) * rstd * g1.w + b1.w);
}

// =========================================================================
// TF32 GEMM, A-packed + B-packed: C = act(A@B + bias) [+res]
// 3-stage cp.async, block 128x128, 256 threads, warp 32x64.
// OUT_PACK: 0 = row-major C, 1 = A-packed C (feeds another GEMM).
// Smem: 3*(4096 + 4096) floats = 96 KB.
// =========================================================================
#define GEMM_SMEM (3 * (16384 + 16384))

template<int DO_GELU, int DO_RES, int DO_ROUND, int OUT_PACK>
__global__ void __launch_bounds__(256, 2) tc_gemm(
    const float* __restrict__ Ap,            // A-packed, M = 2048
    const float* __restrict__ Bp, int ldb,   // B-packed, ldb = N
    const float* __restrict__ bias,
    const float* __restrict__ res,
    float* __restrict__ C, int ldc, int K) {
    extern __shared__ float smf[];
    float* As = smf;               // 3 x 4096
    float* Bs = smf + 3 * 4096;    // 3 x 4096
    const int tid = threadIdx.x;
    const int m0 = blockIdx.y * 128, n0 = blockIdx.x * 128;
    const int NC = K >> 5;

    const unsigned a_dst = (unsigned)__cvta_generic_to_shared(As + tid * 4);
    const unsigned b_dst = (unsigned)__cvta_generic_to_shared(Bs + tid * 4);
    const float* Asrc = Ap + ((size_t)m0 << 3) + tid * 4;
    const float* Bsrc = Bp + ((size_t)n0 << 3) + tid * 4;
    const size_t bkb = (size_t)ldb * 8;

    #define GISSUE(c) do {                                                        \
        int st_ = (c) % 3;                                                        \
        _Pragma("unroll")                                                         \
        for (int i_ = 0; i_ < 4; i_++) {                                          \
            asm volatile("cp.async.ca.shared.global [%0],[%1],16;" ::             \
                "r"(a_dst + st_ * 16384 + i_ * 4096),                             \
                "l"(Asrc + ((size_t)(4 * (c) + i_) << 14)));                      \
            asm volatile("cp.async.ca.shared.global [%0],[%1],16;" ::             \
                "r"(b_dst + st_ * 16384 + i_ * 4096),                             \
                "l"(Bsrc + (size_t)(4 * (c) + i_) * bkb));                        \
        }                                                                         \
    } while (0)

    GISSUE(0); asm volatile("cp.async.commit_group;");
    GISSUE(1); asm volatile("cp.async.commit_group;");

    const int lane = tid & 31, wid = tid >> 5;
    const int g = lane >> 2, tg = lane & 3;
    const int wm = (wid & 3) * 32, wn = (wid >> 2) * 64;
    float acc[2][8][4] = {};

    for (int c = 0; c < NC; c++) {
        if (c + 2 < NC) GISSUE(c + 2);
        asm volatile("cp.async.commit_group;");
        asm volatile("cp.async.wait_group 2;");
        __syncthreads();
        const float* Ast = As + (c % 3) * 4096;
        const float* Bst = Bs + (c % 3) * 4096;
        #pragma unroll
        for (int kb = 0; kb < 4; kb++) {
            unsigned afr[2][4], bfr[8][2];
            #pragma unroll
            for (int mt = 0; mt < 2; mt++) {
                int m = wm + mt * 16 + g;
                float2 lo = *(const float2*)(Ast + kb * 1024 + m * 8 + tg * 2);
                float2 hi = *(const float2*)(Ast + kb * 1024 + m * 8 + 64 + tg * 2);
                afr[mt][0] = __float_as_uint(lo.x);
                afr[mt][1] = __float_as_uint(hi.x);
                afr[mt][2] = __float_as_uint(lo.y);
                afr[mt][3] = __float_as_uint(hi.y);
            }
            #pragma unroll
            for (int j = 0; j < 8; j++) {
                float2 bv = *(const float2*)(Bst + kb * 1024 +
                                             (wn + j * 8 + g) * 8 + tg * 2);
                bfr[j][0] = __float_as_uint(bv.x);
                bfr[j][1] = __float_as_uint(bv.y);
            }
            #pragma unroll
            for (int mt = 0; mt < 2; mt++)
                #pragma unroll
                for (int j = 0; j < 8; j++) mma8(acc[mt][j], afr[mt], bfr[j]);
        }
        __syncthreads();
    }
    #undef GISSUE

    // epilogue
    const int t0m = (((2 * tg) & 3) << 1) | (tg >> 1);
    const int t1m = (((2 * tg + 1) & 3) << 1) | (tg >> 1);
    #pragma unroll
    for (int mt = 0; mt < 2; mt++) {
        int r = m0 + wm + mt * 16 + g;
        #pragma unroll
        for (int j = 0; j < 8; j++) {
            int cidx = n0 + wn + j * 8 + tg * 2;
            float2 bv = *(const float2*)(bias + cidx);
            float2 v0, v1;
            v0.x = acc[mt][j][0] + bv.x; v0.y = acc[mt][j][1] + bv.y;
            v1.x = acc[mt][j][2] + bv.x; v1.y = acc[mt][j][3] + bv.y;
            if (DO_GELU) {
                v0.x = gelu_f(v0.x); v0.y = gelu_f(v0.y);
                v1.x = gelu_f(v1.x); v1.y = gelu_f(v1.y);
            }
            if (DO_RES) {
                float2 r0 = *(const float2*)(res + (size_t)r * ldc + cidx);
                float2 r1 = *(const float2*)(res + (size_t)(r + 8) * ldc + cidx);
                v0.x += r0.x; v0.y += r0.y; v1.x += r1.x; v1.y += r1.y;
            }
            if (DO_ROUND) {
                v0.x = rtf(v0.x); v0.y = rtf(v0.y);
                v1.x = rtf(v1.x); v1.y = rtf(v1.y);
            }
            if (OUT_PACK) {
                float* p0 = C + ((size_t)(cidx >> 3) << 14) + (size_t)r * 8;
                float* p1 = p0 + 64;
                p0[t0m] = v0.x; p0[t1m] = v0.y;
                p1[t0m] = v1.x; p1[t1m] = v1.y;
            } else {
                *(float2*)(C + (size_t)r * ldc + cidx) = v0;
                *(float2*)(C + (size_t)(r + 8) * ldc + cidx) = v1;
            }
        }
    }
}

// =========================================================================
// Flash attention (tf32 HMMA). Inputs row-major; output ctx A-PACKED.
// smem: Qs 16384 | Ks 2x8192 | Vs 64x136 | Ps 8192  = 49664 floats (194 KB)
// =========================================================================
#define FLASH_SMEM (49664 * 4)

template<int CAUSAL>
__global__ void __launch_bounds__(256) flash_kernel(
    const float* __restrict__ Q, int ldq,
    const float* __restrict__ Kg, int ldk,
    const float* __restrict__ Vg, int ldv,
    float* __restrict__ O /* packed ctx base */, int skv, float scale) {
    extern __shared__ float sm[];
    float* Qs = sm;
    float* Ks = sm + 16384;
    float* Vs = sm + 32768;
    float* Ps = sm + 41472;
    const int tid = threadIdx.x;
    const int lane = tid & 31, wid = tid >> 5;
    const int g = lane >> 2, tg = lane & 3;
    const int mb = blockIdx.x, z = blockIdx.y;
    const int bb = z / NHH, h = z % NHH;
    const int m0 = mb * 128;
    const float* Qb = Q + (size_t)bb * SS * ldq + h * HDD;
    const float* Kb = Kg + (size_t)bb * skv * ldk + h * HDD;
    const float* Vb = Vg + (size_t)bb * skv * ldv + h * HDD;

    const int r8 = tid >> 3;
    const int c4 = (tid & 7) << 2;
    const int swb = c4 >> 2;

    #pragma unroll
    for (int u = 0; u < 4; u++) {
        int row = r8 + u * 32;
        unsigned dbase = (unsigned)__cvta_generic_to_shared(
            Qs + row * 32 + (((swb ^ (row & 7)) << 2)));
        const float* src = Qb + (size_t)(m0 + row) * ldq + c4;
        #pragma unroll
        for (int c = 0; c < 4; c++)
            asm volatile("cp.async.ca.shared.global [%0],[%1],16;" ::
                "r"(dbase + c * 16384), "l"(src + c * 32));
    }
    asm volatile("cp.async.commit_group;");

    #define ISSUE_K(it, buf) do {                                                  \
        float* kd_ = Ks + (buf) * 8192;                                            \
        _Pragma("unroll")                                                          \
        for (int u_ = 0; u_ < 2; u_++) {                                           \
            int row_ = r8 + u_ * 32;                                               \
            unsigned db_ = (unsigned)__cvta_generic_to_shared(                     \
                kd_ + row_ * 32 + (((swb ^ (row_ & 7)) << 2)));                    \
            const float* sp_ = Kb + (size_t)((it) * 64 + row_) * ldk + c4;         \
            _Pragma("unroll")                                                      \
            for (int c_ = 0; c_ < 4; c_++)                                         \
                asm volatile("cp.async.ca.shared.global [%0],[%1],16;" ::          \
                    "r"(db_ + c_ * 8192), "l"(sp_ + c_ * 32));                     \
        }                                                                          \
    } while (0)

    #define ISSUE_V(it) do {                                                       \
        _Pragma("unroll")                                                          \
        for (int u_ = 0; u_ < 2; u_++) {                                           \
            int row_ = r8 + u_ * 32;                                               \
            unsigned db_ = (unsigned)__cvta_generic_to_shared(Vs + row_ * 136 + c4);\
            const float* sp_ = Vb + (size_t)((it) * 64 + row_) * ldv + c4;         \
            _Pragma("unroll")                                                      \
            for (int c_ = 0; c_ < 4; c_++)                                         \
                asm volatile("cp.async.ca.shared.global [%0],[%1],16;" ::          \
                    "r"(db_ + c_ * 128), "l"(sp_ + c_ * 32));                      \
        }                                                                          \
    } while (0)

    ISSUE_K(0, 0);
    asm volatile("cp.async.commit_group;");
    asm volatile("cp.async.wait_group 0;");
    __syncthreads();

    const int nkv = CAUSAL ? (2 * mb + 2) : (skv >> 6);
    float m_r[2] = {-1e30f, -1e30f};
    float l_r[2] = {0.f, 0.f};
    float acc_o[16][4] = {};
    const int mrow = wid * 16 + g;

    for (int it = 0; it < nkv; it++) {
        __syncthreads();
        ISSUE_V(it);
        asm volatile("cp.async.commit_group;");
        const bool more = (it + 1 < nkv);
        if (more) {
            ISSUE_K(it + 1, (it + 1) & 1);
            asm volatile("cp.async.commit_group;");
        }
        if (more) asm volatile("cp.async.wait_group 2;");
        else      asm volatile("cp.async.wait_group 1;");
        __syncthreads();

        float acc_s[8][4] = {};
        const float* Ksb = Ks + (it & 1) * 8192;
        #pragma unroll
        for (int c = 0; c < 4; c++) {
            const float* Qc = Qs + c * 4096;
            const float* Kc = Ksb + c * 2048;
            #pragma unroll
            for (int k8 = 0; k8 < 32; k8 += 8) {
                unsigned afr[4], bfr[8][2];
                afr[0] = __float_as_uint(Qc[aswz(mrow,     k8 + tg)]);
                afr[1] = __float_as_uint(Qc[aswz(mrow + 8, k8 + tg)]);
                afr[2] = __float_as_uint(Qc[aswz(mrow,     k8 + tg + 4)]);
                afr[3] = __float_as_uint(Qc[aswz(mrow + 8, k8 + tg + 4)]);
                #pragma unroll
                for (int j = 0; j < 8; j++) {
                    bfr[j][0] = __float_as_uint(Kc[aswz(j * 8 + g, k8 + tg)]);
                    bfr[j][1] = __float_as_uint(Kc[aswz(j * 8 + g, k8 + tg + 4)]);
                }
                #pragma unroll
                for (int j = 0; j < 8; j++) mma8(acc_s[j], afr, bfr[j]);
            }
        }

        const bool diag = CAUSAL && (it >= 2 * mb);
        #pragma unroll
        for (int j = 0; j < 8; j++)
            #pragma unroll
            for (int e = 0; e < 4; e++) {
                float s = acc_s[j][e] * scale;
                if (diag) {
                    int col = it * 64 + j * 8 + tg * 2 + (e & 1);
                    int row = m0 + mrow + (e >> 1) * 8;
                    if (col > row) s = -1e30f;
                }
                acc_s[j][e] = s;
            }

        #pragma unroll
        for (int half = 0; half < 2; half++) {
            float bm = -1e30f;
            #pragma unroll
            for (int j = 0; j < 8; j++)
                bm = fmaxf(bm, fmaxf(acc_s[j][half * 2], acc_s[j][half * 2 + 1]));
            bm = fmaxf(bm, __shfl_xor_sync(0xffffffffu, bm, 1));
            bm = fmaxf(bm, __shfl_xor_sync(0xffffffffu, bm, 2));
            float mnew = fmaxf(m_r[half], bm);
            float alpha = __expf(m_r[half] - mnew);
            float sum = 0.f;
            #pragma unroll
            for (int j = 0; j < 8; j++) {
                float p0 = __expf(acc_s[j][half * 2]     - mnew);
                float p1 = __expf(acc_s[j][half * 2 + 1] - mnew);
                acc_s[j][half * 2]     = p0;
                acc_s[j][half * 2 + 1] = p1;
                sum += p0 + p1;
            }
            sum += __shfl_xor_sync(0xffffffffu, sum, 1);
            sum += __shfl_xor_sync(0xffffffffu, sum, 2);
            l_r[half] = l_r[half] * alpha + sum;
            m_r[half] = mnew;
            #pragma unroll
            for (int j = 0; j < 16; j++) {
                acc_o[j][half * 2]     *= alpha;
                acc_o[j][half * 2 + 1] *= alpha;
            }
        }

        #pragma unroll
        for (int half = 0; half < 2; half++) {
            int row = mrow + half * 8;
            #pragma unroll
            for (int j = 0; j < 8; j++) {
                int col = j * 8 + tg * 2;
                float2 pv;
                pv.x = rtf(acc_s[j][half * 2]);
                pv.y = rtf(acc_s[j][half * 2 + 1]);
                *(float2*)(Ps + (col >> 5) * 4096 + aswz(row, col & 31)) = pv;
            }
        }
        __syncwarp();

        if (more) asm volatile("cp.async.wait_group 1;");
        else      asm volatile("cp.async.wait_group 0;");
        __syncthreads();

        #pragma unroll
        for (int kc = 0; kc < 2; kc++) {
            const float* Pc = Ps + kc * 4096;
            #pragma unroll
            for (int k8 = 0; k8 < 32; k8 += 8) {
                int vr = kc * 32 + k8;
                unsigned afr[4], bfr[16][2];
                afr[0] = __float_as_uint(Pc[aswz(mrow,     k8 + tg)]);
                afr[1] = __float_as_uint(Pc[aswz(mrow + 8, k8 + tg)]);
                afr[2] = __float_as_uint(Pc[aswz(mrow,     k8 + tg + 4)]);
                afr[3] = __float_as_uint(Pc[aswz(mrow + 8, k8 + tg + 4)]);
                #pragma unroll
                for (int j = 0; j < 16; j++) {
                    bfr[j][0] = __float_as_uint(Vs[(vr + tg) * 136 + j * 8 + g]);
                    bfr[j][1] = __float_as_uint(Vs[(vr + tg + 4) * 136 + j * 8 + g]);
                }
                #pragma unroll
                for (int j = 0; j < 16; j++) mma8(acc_o[j], afr, bfr[j]);
            }
        }
    }
    #undef ISSUE_K
    #undef ISSUE_V

    // ---- epilogue: O /= l, round tf32, write A-PACKED ctx ----
    // global col k = h*128 + j*8 + tg*2  ->  group h*16 + j, words t0m/t1m
    float inv[2] = {1.f / l_r[0], 1.f / l_r[1]};
    const int t0m = (((2 * tg) & 3) << 1) | (tg >> 1);
    const int t1m = (((2 * tg + 1) & 3) << 1) | (tg >> 1);
    float* CtxB = O + ((size_t)(h * 16) << 14);
    #pragma unroll
    for (int half = 0; half < 2; half++) {
        int r = bb * SS + m0 + mrow + half * 8;
        #pragma unroll
        for (int j = 0; j < 16; j++) {
            float* p = CtxB + ((size_t)j << 14) + (size_t)r * 8;
            p[t0m] = rtf(acc_o[j][half * 2]     * inv[half]);
            p[t1m] = rtf(acc_o[j][half * 2 + 1] * inv[half]);
        }
    }
}

// ---------------- host orchestration ----------------
extern "C" void kernel_launch(void* const* d_in, const int* in_sizes, int n_in,
                              void* d_out, int out_size) {
    const float* hs    = (const float*)d_in[0];
    const float* enc   = (const float*)d_in[1];
    // d_in[2] = ltor (tril, structural), d_in[3] = cross mask (ones)
    const float* ln1_s = (const float*)d_in[4];
    const float* ln1_b = (const float*)d_in[5];
    const float* w_qkv = (const float*)d_in[6];
    const float* b_qkv = (const float*)d_in[7];
    const float* w_ao  = (const float*)d_in[8];
    const float* b_ao  = (const float*)d_in[9];
    const float* ln2_s = (const float*)d_in[10];
    const float* ln2_b = (const float*)d_in[11];
    const float* w_q   = (const float*)d_in[12];
    const float* b_q   = (const float*)d_in[13];
    const float* w_kv  = (const float*)d_in[14];
    const float* b_kv  = (const float*)d_in[15];
    const float* w_co  = (const float*)d_in[16];
    const float* b_co  = (const float*)d_in[17];
    const float* ln3_s = (const float*)d_in[18];
    const float* ln3_b = (const float*)d_in[19];
    const float* w1    = (const float*)d_in[20];
    const float* b1    = (const float*)d_in[21];
    const float* w2    = (const float*)d_in[22];
    const float* b2    = (const float*)d_in[23];
    float* out = (float*)d_out;

    float *ln, *qkv, *ctx, *x, *qb, *kvb, *mlp, *encr, *wbuf;
    cudaGetSymbolAddress((void**)&ln,   g_ln);
    cudaGetSymbolAddress((void**)&qkv,  g_qkv);
    cudaGetSymbolAddress((void**)&ctx,  g_ctx);
    cudaGetSymbolAddress((void**)&x,    g_x);
    cudaGetSymbolAddress((void**)&qb,   g_q);
    cudaGetSymbolAddress((void**)&kvb,  g_kv);
    cudaGetSymbolAddress((void**)&mlp,  g_mlp);
    cudaGetSymbolAddress((void**)&encr, g_enc);
    cudaGetSymbolAddress((void**)&wbuf, g_w);

    float* wr_qkv = wbuf;
    float* wr_ao  = wr_qkv + 2048u * 6144;
    float* wr_q   = wr_ao  + 2048u * 2048;
    float* wr_kv  = wr_q   + 2048u * 2048;
    float* wr_co  = wr_kv  + 2048u * 4096;
    float* wr_w1  = wr_co  + 2048u * 2048;
    float* wr_w2  = wr_w1  + 2048u * 8192;

    cudaFuncSetAttribute(tc_gemm<0, 0, 1, 0>, cudaFuncAttributeMaxDynamicSharedMemorySize, GEMM_SMEM);
    cudaFuncSetAttribute(tc_gemm<0, 1, 0, 0>, cudaFuncAttributeMaxDynamicSharedMemorySize, GEMM_SMEM);
    cudaFuncSetAttribute(tc_gemm<1, 0, 1, 1>, cudaFuncAttributeMaxDynamicSharedMemorySize, GEMM_SMEM);
    cudaFuncSetAttribute(flash_kernel<0>, cudaFuncAttributeMaxDynamicSharedMemorySize, FLASH_SMEM);
    cudaFuncSetAttribute(flash_kernel<1>, cudaFuncAttributeMaxDynamicSharedMemorySize, FLASH_SMEM);

    const float scale = 0.08838834764831845f;  // 1/sqrt(128)
    dim3 thr(256);

    // ---- prep: fragment-pack weights, A-pack encoder ----
    packw_kernel<<<1184, thr>>>(w_qkv, wr_qkv, 2048, 6144);
    packw_kernel<<<1184, thr>>>(w_ao,  wr_ao,  2048, 2048);
    packw_kernel<<<1184, thr>>>(w_q,   wr_q,   2048, 2048);
    packw_kernel<<<1184, thr>>>(w_kv,  wr_kv,  2048, 4096);
    packw_kernel<<<1184, thr>>>(w_co,  wr_co,  2048, 2048);
    packw_kernel<<<1184, thr>>>(w1,    wr_w1,  2048, 8192);
    packw_kernel<<<1184, thr>>>(w2,    wr_w2,  8192, 2048);
    packa_kernel<<<1184, thr>>>(enc, encr, 2048);

    // ---- self attention block ----
    ln_kernel<<<MTOK, thr>>>(hs, ln1_s, ln1_b, ln);
    tc_gemm<0, 0, 1, 0><<<dim3(48, 16), thr, GEMM_SMEM>>>(ln, wr_qkv, 6144, b_qkv, nullptr, qkv, 6144, HH);
    flash_kernel<1><<<dim3(8, 32), thr, FLASH_SMEM>>>(qkv, 6144, qkv + 2048, 6144, qkv + 4096, 6144, ctx, SS, scale);
    tc_gemm<0, 1, 0, 0><<<dim3(16, 16), thr, GEMM_SMEM>>>(ctx, wr_ao, 2048, b_ao, hs, x, HH, HH);

    // ---- cross attention block ----
    ln_kernel<<<MTOK, thr>>>(x, ln2_s, ln2_b, ln);
    tc_gemm<0, 0, 1, 0><<<dim3(16, 16), thr, GEMM_SMEM>>>(ln, wr_q, 2048, b_q, nullptr, qb, HH, HH);
    tc_gemm<0, 0, 1, 0><<<dim3(32, 16), thr, GEMM_SMEM>>>(encr, wr_kv, 4096, b_kv, nullptr, kvb, 4096, HH);
    flash_kernel<0><<<dim3(8, 32), thr, FLASH_SMEM>>>(qb, HH, kvb, 4096, kvb + 2048, 4096, ctx, TT, scale);
    tc_gemm<0, 1, 0, 0><<<dim3(16, 16), thr, GEMM_SMEM>>>(ctx, wr_co, 2048, b_co, x, x, HH, HH);

    // ---- mlp block ----
    ln_kernel<<<MTOK, thr>>>(x, ln3_s, ln3_b, ln);
    tc_gemm<1, 0, 1, 1><<<dim3(64, 16), thr, GEMM_SMEM>>>(ln, wr_w1, 8192, b1, nullptr, mlp, 8192, HH);
    tc_gemm<0, 1, 0, 0><<<dim3(16, 16), thr, GEMM_SMEM>>>(mlp, wr_w2, 2048, b2, x, out, HH, 8192);
}

// round 9
// speedup vs baseline: 1.7206x; 1.7206x over previous
#include <cuda_runtime.h>
#include <cuda_fp16.h>
#include <math.h>

// ---------------- problem constants ----------------
#define BB   2
#define SS   1024
#define TT   1024
#define HH   2048
#define NHH  16
#define HDD  128
#define MTOK 2048

// ---------------- device scratch (reinterpreted as half where noted) ----------------
__device__ float g_ln  [2048u * 1024];   // half: ln out [2048][2048]
__device__ float g_qkv [2048u * 3072];   // half: qkv [2048][6144]
__device__ float g_ctx [2048u * 1024];   // half: ctx [2048][2048]
__device__ float g_x   [2048u * 2048];   // float residual stream
__device__ float g_q   [2048u * 1024];   // half: q [2048][2048]
__device__ float g_kv  [2048u * 2048];   // half: kv [2048][4096]
__device__ float g_mlp [2048u * 4096];   // half: mlp [2048][8192]
__device__ float g_enc [2048u * 1024];   // half: enc [2048][2048]
__device__ float g_vt  [2048u * 2048];   // half: V^T [32][128][1024]
__device__ float g_w   [40u * 1024 * 1024]; // u32: packed half weights (33.5M u32)

// ---------------- helpers ----------------
__device__ __forceinline__ unsigned pack2(float x, float y) {
    __half2 h = __floats2half2_rn(x, y);
    return *(unsigned*)&h;
}
// XOR-swizzled [row][32]u32 layout
__device__ __forceinline__ int aswz(int m, int k) {
    return m * 32 + (((((k) >> 2) ^ (m & 7)) << 2) | (k & 3));
}
__device__ __forceinline__ void mma16816(float* c, const unsigned* a, const unsigned* b) {
    asm volatile(
        "mma.sync.aligned.m16n8k16.row.col.f32.f16.f16.f32 "
        "{%0,%1,%2,%3}, {%4,%5,%6,%7}, {%8,%9}, {%0,%1,%2,%3};"
        : "+f"(c[0]), "+f"(c[1]), "+f"(c[2]), "+f"(c[3])
        : "r"(a[0]), "r"(a[1]), "r"(a[2]), "r"(a[3]), "r"(b[0]), "r"(b[1]));
}
__device__ __forceinline__ float gelu_f(float u) {
    return 0.5f * u * (1.f + tanhf(0.7978845608028654f * u * (1.f + 0.044715f * u * u)));
}

// ---------------- reductions ----------------
__device__ __forceinline__ float blockReduceSum(float v, float* sh) {
    int lane = threadIdx.x & 31, w = threadIdx.x >> 5;
    #pragma unroll
    for (int o = 16; o > 0; o >>= 1) v += __shfl_xor_sync(0xffffffffu, v, o);
    if (lane == 0) sh[w] = v;
    __syncthreads();
    float r = 0.f;
    if (w == 0) {
        r = (lane < (blockDim.x >> 5)) ? sh[lane] : 0.f;
        #pragma unroll
        for (int o = 16; o > 0; o >>= 1) r += __shfl_xor_sync(0xffffffffu, r, o);
        if (lane == 0) sh[0] = r;
    }
    __syncthreads();
    r = sh[0];
    __syncthreads();
    return r;
}

// =========================================================================
// Weight pack: W[K][N] float -> half fragment layout, coalesced both sides.
// Bh[(k>>4)*N*8 + (n>>2)*32 + (n&3)*8 + tg*2 + r]:
//   word tg*2+0 = halves (k16+2tg, k16+2tg+1), tg*2+1 = (k16+2tg+8, +9)
// =========================================================================
__global__ void __launch_bounds__(256) packw_kernel(const float* __restrict__ W,
                                                    unsigned* __restrict__ P,
                                                    int K, int N) {
    int nq = N >> 2;
    int total = (K >> 4) * nq;
    for (int idx = blockIdx.x * blockDim.x + threadIdx.x; idx < total;
         idx += gridDim.x * blockDim.x) {
        int kb = idx / nq;
        int n0 = (idx - kb * nq) << 2;
        const float* src = W + (size_t)(kb * 16) * N + n0;
        float4 rv[16];
        #pragma unroll
        for (int r = 0; r < 16; r++) rv[r] = *(const float4*)(src + (size_t)r * N);
        const float* e = (const float*)rv;   // e[k*4 + nn]
        unsigned out[32];
        #pragma unroll
        for (int nn = 0; nn < 4; nn++)
            #pragma unroll
            for (int tg = 0; tg < 4; tg++) {
                out[nn * 8 + tg * 2 + 0] = pack2(e[(2 * tg) * 4 + nn],     e[(2 * tg + 1) * 4 + nn]);
                out[nn * 8 + tg * 2 + 1] = pack2(e[(2 * tg + 8) * 4 + nn], e[(2 * tg + 9) * 4 + nn]);
            }
        uint4* d = (uint4*)(P + (size_t)kb * N * 8 + (size_t)(n0 >> 2) * 32);
        #pragma unroll
        for (int i = 0; i < 8; i++) d[i] = ((uint4*)out)[i];
    }
}

// ---------------- float -> half row-major (encoder states) ----------------
__global__ void __launch_bounds__(256) f2h_kernel(const float2* __restrict__ src,
                                                  unsigned* __restrict__ dst, int n2) {
    for (int i = blockIdx.x * blockDim.x + threadIdx.x; i < n2;
         i += gridDim.x * blockDim.x) {
        float2 v = src[i];
        dst[i] = pack2(v.x, v.y);
    }
}

// ---------------- layernorm: float in -> half row-major out ----------------
__global__ void __launch_bounds__(256) ln_kernel(const float* __restrict__ x,
                                                 const float* __restrict__ gw,
                                                 const float* __restrict__ gb,
                                                 __half* __restrict__ out) {
    __shared__ float sh[32];
    size_t base = (size_t)blockIdx.x * HH;
    int tid = threadIdx.x;
    float4 a = *(const float4*)(x + base + tid * 4);
    float4 b = *(const float4*)(x + base + 1024 + tid * 4);
    float s = a.x + a.y + a.z + a.w + b.x + b.y + b.z + b.w;
    s = blockReduceSum(s, sh);
    float mean = s * (1.f / HH);
    float d, sq = 0.f;
    d = a.x - mean; sq += d * d; d = a.y - mean; sq += d * d;
    d = a.z - mean; sq += d * d; d = a.w - mean; sq += d * d;
    d = b.x - mean; sq += d * d; d = b.y - mean; sq += d * d;
    d = b.z - mean; sq += d * d; d = b.w - mean; sq += d * d;
    sq = blockReduceSum(sq, sh);
    float rstd = rsqrtf(sq * (1.f / HH) + 1e-5f);
    float4 g0 = *(const float4*)(gw + tid * 4);
    float4 g1 = *(const float4*)(gw + 1024 + tid * 4);
    float4 b0 = *(const float4*)(gb + tid * 4);
    float4 b1 = *(const float4*)(gb + 1024 + tid * 4);
    uint2 o0, o1;
    o0.x = pack2((a.x - mean) * rstd * g0.x + b0.x, (a.y - mean) * rstd * g0.y + b0.y);
    o0.y = pack2((a.z - mean) * rstd * g0.z + b0.z, (a.w - mean) * rstd * g0.w + b0.w);
    o1.x = pack2((b.x - mean) * rstd * g1.x + b1.x, (b.y - mean) * rstd * g1.y + b1.y);
    o1.y = pack2((b.z - mean) * rstd * g1.z + b1.z, (b.w - mean) * rstd * g1.w + b1.w);
    *(uint2*)(out + base + tid * 4)        = o0;
    *(uint2*)(out + base + 1024 + tid * 4) = o1;
}

// ---------------- V transpose: [token][dim-slice] -> Vt[bh][dim][token] ----------------
__global__ void __launch_bounds__(256) vtrans_kernel(const __half* __restrict__ src, int lds,
                                                     __half* __restrict__ dst) {
    __shared__ __half t[32][33];
    int z = blockIdx.z;
    int bb = z >> 4, h = z & 15;
    int t0 = blockIdx.x * 32, d0 = blockIdx.y * 32;
    int tx = threadIdx.x & 31, ty = threadIdx.x >> 5;   // 32 x 8
    const __half* s = src + (size_t)(bb * SS + t0 + ty) * lds + h * HDD + d0 + tx;
    #pragma unroll
    for (int r = 0; r < 4; r++)
        t[ty + 8 * r][tx] = s[(size_t)(8 * r) * lds];
    __syncthreads();
    __half* d = dst + (size_t)z * HDD * SS + (size_t)(d0 + ty) * SS + t0 + tx;
    #pragma unroll
    for (int r = 0; r < 4; r++)
        d[(size_t)(8 * r) * SS] = t[tx][ty + 8 * r];
}

// =========================================================================
// FP16 GEMM: C = act(A@B + bias) [+res]. A half row-major, B packed.
// Block 128x128, BK=64 halves, 3-stage cp.async, 256 thr, warp 32x64.
// Smem: 3 * (16KB A + 16KB B) = 96KB.
// =========================================================================
#define GEMM_SMEM (3 * (16384 + 16384))

template<int DO_GELU, int DO_RES, int OUT_HALF>
__global__ void __launch_bounds__(256, 2) tc_gemm(
    const __half* __restrict__ Ap, int lda,
    const unsigned* __restrict__ Bp, int N,
    const float* __restrict__ bias,
    const float* __restrict__ res,
    void* __restrict__ Cv, int ldc, int K) {
    extern __shared__ unsigned smu[];
    unsigned* As = smu;             // 3 x 4096 u32
    unsigned* Bs = smu + 12288;     // 3 x 4096 u32
    const int tid = threadIdx.x;
    const int m0 = blockIdx.y * 128, n0 = blockIdx.x * 128;
    const int NC = K >> 6;

    const int arow = tid >> 1;
    unsigned a_base = (unsigned)__cvta_generic_to_shared(As) + arow * 128;
    unsigned b_base = (unsigned)__cvta_generic_to_shared(Bs) + tid * 16;
    unsigned a_off[4];
    #pragma unroll
    for (int i = 0; i < 4; i++) {
        int j = (tid & 1) * 4 + i;
        a_off[i] = ((j ^ (arow & 7)) * 16);
    }
    const __half* Asrc = Ap + (size_t)(m0 + arow) * lda + (tid & 1) * 32;
    const unsigned* Bsrc = Bp + (size_t)n0 * 8 + tid * 4;
    const size_t bk16 = (size_t)N * 8;

    #define GISSUE(c) do {                                                        \
        int st_ = (c) % 3;                                                        \
        const __half* ap_ = Asrc + (c) * 64;                                      \
        _Pragma("unroll")                                                         \
        for (int i_ = 0; i_ < 4; i_++) {                                          \
            asm volatile("cp.async.ca.shared.global [%0],[%1],16;" ::             \
                "r"(a_base + st_ * 16384 + a_off[i_]), "l"(ap_ + i_ * 8));        \
            asm volatile("cp.async.ca.shared.global [%0],[%1],16;" ::             \
                "r"(b_base + st_ * 16384 + i_ * 4096),                            \
                "l"(Bsrc + (size_t)(4 * (c) + i_) * bk16));                       \
        }                                                                         \
    } while (0)

    GISSUE(0); asm volatile("cp.async.commit_group;");
    GISSUE(1); asm volatile("cp.async.commit_group;");

    const int lane = tid & 31, wid = tid >> 5;
    const int g = lane >> 2, tg = lane & 3;
    const int wm = (wid & 3) * 32, wn = (wid >> 2) * 64;
    const int nbase = wn * 8 + (g >> 2) * 32 + (g & 3) * 8 + 2 * tg;
    float acc[2][8][4] = {};

    for (int c = 0; c < NC; c++) {
        if (c + 2 < NC) GISSUE(c + 2);
        asm volatile("cp.async.commit_group;");
        asm volatile("cp.async.wait_group 2;");
        __syncthreads();
        const unsigned* Ast = As + (c % 3) * 4096;
        const unsigned* Bst = Bs + (c % 3) * 4096;
        #pragma unroll
        for (int kk = 0; kk < 4; kk++) {
            unsigned afr[2][4], bfr[8][2];
            #pragma unroll
            for (int mt = 0; mt < 2; mt++) {
                int m = wm + mt * 16 + g;
                afr[mt][0] = Ast[aswz(m,     8 * kk + tg)];
                afr[mt][1] = Ast[aswz(m + 8, 8 * kk + tg)];
                afr[mt][2] = Ast[aswz(m,     8 * kk + tg + 4)];
                afr[mt][3] = Ast[aswz(m + 8, 8 * kk + tg + 4)];
            }
            #pragma unroll
            for (int j = 0; j < 8; j++) {
                uint2 bv = *(const uint2*)(Bst + kk * 1024 + nbase + j * 64);
                bfr[j][0] = bv.x; bfr[j][1] = bv.y;
            }
            #pragma unroll
            for (int mt = 0; mt < 2; mt++)
                #pragma unroll
                for (int j = 0; j < 8; j++) mma16816(acc[mt][j], afr[mt], bfr[j]);
        }
        __syncthreads();
    }
    #undef GISSUE

    // epilogue
    #pragma unroll
    for (int mt = 0; mt < 2; mt++) {
        int r = m0 + wm + mt * 16 + g;
        #pragma unroll
        for (int j = 0; j < 8; j++) {
            int cidx = n0 + wn + j * 8 + tg * 2;
            float2 bv = *(const float2*)(bias + cidx);
            float2 v0, v1;
            v0.x = acc[mt][j][0] + bv.x; v0.y = acc[mt][j][1] + bv.y;
            v1.x = acc[mt][j][2] + bv.x; v1.y = acc[mt][j][3] + bv.y;
            if (DO_GELU) {
                v0.x = gelu_f(v0.x); v0.y = gelu_f(v0.y);
                v1.x = gelu_f(v1.x); v1.y = gelu_f(v1.y);
            }
            if (DO_RES) {
                float2 r0 = *(const float2*)(res + (size_t)r * ldc + cidx);
                float2 r1 = *(const float2*)(res + (size_t)(r + 8) * ldc + cidx);
                v0.x += r0.x; v0.y += r0.y; v1.x += r1.x; v1.y += r1.y;
            }
            if (OUT_HALF) {
                __half* Ch = (__half*)Cv;
                *(unsigned*)(Ch + (size_t)r * ldc + cidx)       = pack2(v0.x, v0.y);
                *(unsigned*)(Ch + (size_t)(r + 8) * ldc + cidx) = pack2(v1.x, v1.y);
            } else {
                float* Cf = (float*)Cv;
                *(float2*)(Cf + (size_t)r * ldc + cidx) = v0;
                *(float2*)(Cf + (size_t)(r + 8) * ldc + cidx) = v1;
            }
        }
    }
}

// =========================================================================
// FP16 flash attention. Q,K half row-major; V pre-transposed [bh][dim][key].
// Q-block 128/CTA, KV blocks of 64. 8 warps x 16 q-rows.
// smem u32: Q 2x4096 | K 2bufs x 4096 | V 4096 | P 4096 = 24576 u32 = 96KB
// =========================================================================
#define FLASH_SMEM (24576 * 4)

template<int CAUSAL>
__global__ void __launch_bounds__(256) flash_kernel(
    const __half* __restrict__ Q, int ldq,
    const __half* __restrict__ Kg, int ldk,
    const __half* __restrict__ Vt,
    __half* __restrict__ O, int skv, float scale) {
    extern __shared__ unsigned smu[];
    unsigned* Qu = smu;            // 2 chunks x 4096
    unsigned* Ku = smu + 8192;     // 2 bufs x (2 chunks x 2048)
    unsigned* Vu = smu + 16384;    // 4096
    unsigned* Pu = smu + 20480;    // 4096
    const unsigned q_sb = (unsigned)__cvta_generic_to_shared(Qu);
    const unsigned k_sb = (unsigned)__cvta_generic_to_shared(Ku);
    const unsigned v_sb = (unsigned)__cvta_generic_to_shared(Vu);
    const int tid = threadIdx.x;
    const int lane = tid & 31, wid = tid >> 5;
    const int g = lane >> 2, tg = lane & 3;
    const int mb = blockIdx.x, z = blockIdx.y;
    const int bb = z / NHH, h = z % NHH;
    const int m0 = mb * 128;
    const __half* Qb = Q + (size_t)bb * SS * ldq + h * HDD;
    const __half* Kb = Kg + (size_t)bb * skv * ldk + h * HDD;
    const __half* Vb = Vt + (size_t)z * HDD * SS;
    __half* Ob = O + (size_t)bb * SS * HH + h * HDD;

    // ---- load Q (128 x 128 halves) ----
    {
        int row = tid >> 1;
        const __half* src = Qb + (size_t)(m0 + row) * ldq;
        unsigned db = q_sb + row * 128;
        #pragma unroll
        for (int i = 0; i < 8; i++) {
            int jj = (tid & 1) * 8 + i;
            asm volatile("cp.async.ca.shared.global [%0],[%1],16;" ::
                "r"(db + (jj >> 3) * 16384 + (((jj & 7) ^ (row & 7)) * 16)),
                "l"(src + jj * 8));
        }
    }
    asm volatile("cp.async.commit_group;");

    #define ISSUE_K(it, buf) do {                                                  \
        int row_ = tid >> 2;                                                       \
        const __half* sp_ = Kb + (size_t)((it) * 64 + row_) * ldk;                 \
        unsigned db_ = k_sb + (buf) * 16384 + row_ * 128;                          \
        _Pragma("unroll")                                                          \
        for (int i_ = 0; i_ < 4; i_++) {                                           \
            int jj_ = (tid & 3) * 4 + i_;                                          \
            asm volatile("cp.async.ca.shared.global [%0],[%1],16;" ::              \
                "r"(db_ + (jj_ >> 3) * 8192 + (((jj_ & 7) ^ (row_ & 7)) * 16)),    \
                "l"(sp_ + jj_ * 8));                                               \
        }                                                                          \
    } while (0)

    #define ISSUE_V(it) do {                                                       \
        int row_ = tid >> 1;                                                       \
        const __half* sp_ = Vb + (size_t)row_ * SS + (it) * 64;                    \
        unsigned db_ = v_sb + row_ * 128;                                          \
        _Pragma("unroll")                                                          \
        for (int i_ = 0; i_ < 4; i_++) {                                           \
            int jj_ = (tid & 1) * 4 + i_;                                          \
            asm volatile("cp.async.ca.shared.global [%0],[%1],16;" ::              \
                "r"(db_ + ((jj_ ^ (row_ & 7)) * 16)), "l"(sp_ + jj_ * 8));         \
        }                                                                          \
    } while (0)

    ISSUE_K(0, 0);
    asm volatile("cp.async.commit_group;");
    asm volatile("cp.async.wait_group 0;");
    __syncthreads();

    const int nkv = CAUSAL ? (2 * mb + 2) : (skv >> 6);
    float m_r[2] = {-1e30f, -1e30f};
    float l_r[2] = {0.f, 0.f};
    float acc_o[16][4] = {};
    const int mrow = wid * 16 + g;

    for (int it = 0; it < nkv; it++) {
        __syncthreads();   // protect Vu / K-buffer reuse
        ISSUE_V(it);
        asm volatile("cp.async.commit_group;");
        const bool more = (it + 1 < nkv);
        if (more) {
            ISSUE_K(it + 1, (it + 1) & 1);
            asm volatile("cp.async.commit_group;");
        }
        if (more) asm volatile("cp.async.wait_group 2;");
        else      asm volatile("cp.async.wait_group 1;");
        __syncthreads();

        // ---- S = Q K^T (16 x 64 per warp) ----
        float acc_s[8][4] = {};
        #pragma unroll
        for (int cq = 0; cq < 2; cq++) {
            const unsigned* Qc = Qu + cq * 4096;
            const unsigned* Kc = Ku + (it & 1) * 4096 + cq * 2048;
            #pragma unroll
            for (int kk = 0; kk < 4; kk++) {
                unsigned afr[4], bfr[8][2];
                afr[0] = Qc[aswz(mrow,     8 * kk + tg)];
                afr[1] = Qc[aswz(mrow + 8, 8 * kk + tg)];
                afr[2] = Qc[aswz(mrow,     8 * kk + tg + 4)];
                afr[3] = Qc[aswz(mrow + 8, 8 * kk + tg + 4)];
                #pragma unroll
                for (int j = 0; j < 8; j++) {
                    bfr[j][0] = Kc[aswz(j * 8 + g, 8 * kk + tg)];
                    bfr[j][1] = Kc[aswz(j * 8 + g, 8 * kk + tg + 4)];
                }
                #pragma unroll
                for (int j = 0; j < 8; j++) mma16816(acc_s[j], afr, bfr[j]);
            }
        }

        // ---- scale + causal mask ----
        const bool diag = CAUSAL && (it >= 2 * mb);
        #pragma unroll
        for (int j = 0; j < 8; j++)
            #pragma unroll
            for (int e = 0; e < 4; e++) {
                float s = acc_s[j][e] * scale;
                if (diag) {
                    int col = it * 64 + j * 8 + tg * 2 + (e & 1);
                    int row = m0 + mrow + (e >> 1) * 8;
                    if (col > row) s = -1e30f;
                }
                acc_s[j][e] = s;
            }

        // ---- online softmax ----
        #pragma unroll
        for (int half = 0; half < 2; half++) {
            float bm = -1e30f;
            #pragma unroll
            for (int j = 0; j < 8; j++)
                bm = fmaxf(bm, fmaxf(acc_s[j][half * 2], acc_s[j][half * 2 + 1]));
            bm = fmaxf(bm, __shfl_xor_sync(0xffffffffu, bm, 1));
            bm = fmaxf(bm, __shfl_xor_sync(0xffffffffu, bm, 2));
            float mnew = fmaxf(m_r[half], bm);
            float alpha = __expf(m_r[half] - mnew);
            float sum = 0.f;
            #pragma unroll
            for (int j = 0; j < 8; j++) {
                float p0 = __expf(acc_s[j][half * 2]     - mnew);
                float p1 = __expf(acc_s[j][half * 2 + 1] - mnew);
                acc_s[j][half * 2]     = p0;
                acc_s[j][half * 2 + 1] = p1;
                sum += p0 + p1;
            }
            sum += __shfl_xor_sync(0xffffffffu, sum, 1);
            sum += __shfl_xor_sync(0xffffffffu, sum, 2);
            l_r[half] = l_r[half] * alpha + sum;
            m_r[half] = mnew;
            #pragma unroll
            for (int j = 0; j < 16; j++) {
                acc_o[j][half * 2]     *= alpha;
                acc_o[j][half * 2 + 1] *= alpha;
            }
        }

        // ---- store P (half) to swizzled smem ----
        #pragma unroll
        for (int half = 0; half < 2; half++) {
            int row = mrow + half * 8;
            #pragma unroll
            for (int j = 0; j < 8; j++)
                Pu[aswz(row, j * 4 + tg)] =
                    pack2(acc_s[j][half * 2], acc_s[j][half * 2 + 1]);
        }
        __syncwarp();

        if (more) asm volatile("cp.async.wait_group 1;");
        else      asm volatile("cp.async.wait_group 0;");
        __syncthreads();

        // ---- O += P V  (16 x 128 per warp) ----
        #pragma unroll
        for (int kk = 0; kk < 4; kk++) {
            unsigned afr[4], bfr[16][2];
            afr[0] = Pu[aswz(mrow,     8 * kk + tg)];
            afr[1] = Pu[aswz(mrow + 8, 8 * kk + tg)];
            afr[2] = Pu[aswz(mrow,     8 * kk + tg + 4)];
            afr[3] = Pu[aswz(mrow + 8, 8 * kk + tg + 4)];
            #pragma unroll
            for (int j = 0; j < 16; j++) {
                bfr[j][0] = Vu[aswz(j * 8 + g, 8 * kk + tg)];
                bfr[j][1] = Vu[aswz(j * 8 + g, 8 * kk + tg + 4)];
            }
            #pragma unroll
            for (int j = 0; j < 16; j++) mma16816(acc_o[j], afr, bfr[j]);
        }
    }
    #undef ISSUE_K
    #undef ISSUE_V

    // ---- epilogue: O /= l, write ctx half ----
    float inv[2] = {1.f / l_r[0], 1.f / l_r[1]};
    #pragma unroll
    for (int half = 0; half < 2; half++) {
        int r = m0 + mrow + half * 8;
        #pragma unroll
        for (int j = 0; j < 16; j++) {
            int col = j * 8 + tg * 2;
            *(unsigned*)(Ob + (size_t)r * HH + col) =
                pack2(acc_o[j][half * 2] * inv[half], acc_o[j][half * 2 + 1] * inv[half]);
        }
    }
}

// ---------------- host orchestration ----------------
extern "C" void kernel_launch(void* const* d_in, const int* in_sizes, int n_in,
                              void* d_out, int out_size) {
    const float* hs    = (const float*)d_in[0];
    const float* enc   = (const float*)d_in[1];
    // d_in[2] = ltor (tril, structural), d_in[3] = cross mask (ones)
    const float* ln1_s = (const float*)d_in[4];
    const float* ln1_b = (const float*)d_in[5];
    const float* w_qkv = (const float*)d_in[6];
    const float* b_qkv = (const float*)d_in[7];
    const float* w_ao  = (const float*)d_in[8];
    const float* b_ao  = (const float*)d_in[9];
    const float* ln2_s = (const float*)d_in[10];
    const float* ln2_b = (const float*)d_in[11];
    const float* w_q   = (const float*)d_in[12];
    const float* b_q   = (const float*)d_in[13];
    const float* w_kv  = (const float*)d_in[14];
    const float* b_kv  = (const float*)d_in[15];
    const float* w_co  = (const float*)d_in[16];
    const float* b_co  = (const float*)d_in[17];
    const float* ln3_s = (const float*)d_in[18];
    const float* ln3_b = (const float*)d_in[19];
    const float* w1    = (const float*)d_in[20];
    const float* b1    = (const float*)d_in[21];
    const float* w2    = (const float*)d_in[22];
    const float* b2    = (const float*)d_in[23];
    float* out = (float*)d_out;

    void *lnp, *qkvp, *ctxp, *xp, *qp, *kvp, *mlpp, *encp, *vtp, *wp;
    cudaGetSymbolAddress(&lnp,  g_ln);
    cudaGetSymbolAddress(&qkvp, g_qkv);
    cudaGetSymbolAddress(&ctxp, g_ctx);
    cudaGetSymbolAddress(&xp,   g_x);
    cudaGetSymbolAddress(&qp,   g_q);
    cudaGetSymbolAddress(&kvp,  g_kv);
    cudaGetSymbolAddress(&mlpp, g_mlp);
    cudaGetSymbolAddress(&encp, g_enc);
    cudaGetSymbolAddress(&vtp,  g_vt);
    cudaGetSymbolAddress(&wp,   g_w);

    __half* lnh  = (__half*)lnp;
    __half* qkvh = (__half*)qkvp;
    __half* ctxh = (__half*)ctxp;
    float*  x    = (float*)xp;
    __half* qbh  = (__half*)qp;
    __half* kvbh = (__half*)kvp;
    __half* mlph = (__half*)mlpp;
    __half* ench = (__half*)encp;
    __half* vth  = (__half*)vtp;
    unsigned* wh = (unsigned*)wp;

    unsigned* wr_qkv = wh;                          // 2048*6144/2 u32
    unsigned* wr_ao  = wr_qkv + 2048u * 3072;
    unsigned* wr_q   = wr_ao  + 2048u * 1024;
    unsigned* wr_kv  = wr_q   + 2048u * 1024;
    unsigned* wr_co  = wr_kv  + 2048u * 2048;
    unsigned* wr_w1  = wr_co  + 2048u * 1024;
    unsigned* wr_w2  = wr_w1  + 2048u * 4096;

    cudaFuncSetAttribute(tc_gemm<0, 0, 1>, cudaFuncAttributeMaxDynamicSharedMemorySize, GEMM_SMEM);
    cudaFuncSetAttribute(tc_gemm<0, 1, 0>, cudaFuncAttributeMaxDynamicSharedMemorySize, GEMM_SMEM);
    cudaFuncSetAttribute(tc_gemm<1, 0, 1>, cudaFuncAttributeMaxDynamicSharedMemorySize, GEMM_SMEM);
    cudaFuncSetAttribute(flash_kernel<0>, cudaFuncAttributeMaxDynamicSharedMemorySize, FLASH_SMEM);
    cudaFuncSetAttribute(flash_kernel<1>, cudaFuncAttributeMaxDynamicSharedMemorySize, FLASH_SMEM);

    const float scale = 0.08838834764831845f;  // 1/sqrt(128)
    dim3 thr(256);
    dim3 tgrid(32, 4, 32);
    dim3 tthr(256);

    // ---- prep: pack weights (coalesced), convert encoder ----
    packw_kernel<<<1184, thr>>>(w_qkv, wr_qkv, 2048, 6144);
    packw_kernel<<<1184, thr>>>(w_ao,  wr_ao,  2048, 2048);
    packw_kernel<<<1184, thr>>>(w_q,   wr_q,   2048, 2048);
    packw_kernel<<<1184, thr>>>(w_kv,  wr_kv,  2048, 4096);
    packw_kernel<<<1184, thr>>>(w_co,  wr_co,  2048, 2048);
    packw_kernel<<<1184, thr>>>(w1,    wr_w1,  2048, 8192);
    packw_kernel<<<1184, thr>>>(w2,    wr_w2,  8192, 2048);
    f2h_kernel<<<1184, thr>>>((const float2*)enc, (unsigned*)ench, 2048 * 1024);

    // ---- self attention block ----
    ln_kernel<<<MTOK, thr>>>(hs, ln1_s, ln1_b, lnh);
    tc_gemm<0, 0, 1><<<dim3(48, 16), thr, GEMM_SMEM>>>(lnh, HH, wr_qkv, 6144, b_qkv, nullptr, qkvh, 6144, HH);
    vtrans_kernel<<<tgrid, tthr>>>(qkvh + 4096, 6144, vth);
    flash_kernel<1><<<dim3(8, 32), thr, FLASH_SMEM>>>(qkvh, 6144, qkvh + 2048, 6144, vth, ctxh, SS, scale);
    tc_gemm<0, 1, 0><<<dim3(16, 16), thr, GEMM_SMEM>>>(ctxh, HH, wr_ao, 2048, b_ao, hs, x, HH, HH);

    // ---- cross attention block ----
    ln_kernel<<<MTOK, thr>>>(x, ln2_s, ln2_b, lnh);
    tc_gemm<0, 0, 1><<<dim3(16, 16), thr, GEMM_SMEM>>>(lnh, HH, wr_q, 2048, b_q, nullptr, qbh, HH, HH);
    tc_gemm<0, 0, 1><<<dim3(32, 16), thr, GEMM_SMEM>>>(ench, HH, wr_kv, 4096, b_kv, nullptr, kvbh, 4096, HH);
    vtrans_kernel<<<tgrid, tthr>>>(kvbh + 2048, 4096, vth);
    flash_kernel<0><<<dim3(8, 32), thr, FLASH_SMEM>>>(qbh, HH, kvbh, 4096, vth, ctxh, TT, scale);
    tc_gemm<0, 1, 0><<<dim3(16, 16), thr, GEMM_SMEM>>>(ctxh, HH, wr_co, 2048, b_co, x, x, HH, HH);

    // ---- mlp block ----
    ln_kernel<<<MTOK, thr>>>(x, ln3_s, ln3_b, lnh);
    tc_gemm<1, 0, 1><<<dim3(64, 16), thr, GEMM_SMEM>>>(lnh, HH, wr_w1, 8192, b1, nullptr, mlph, 8192, HH);
    tc_gemm<0, 1, 0><<<dim3(16, 16), thr, GEMM_SMEM>>>(mlph, 8192, wr_w2, 2048, b2, x, out, HH, 8192);
}

// round 10
// speedup vs baseline: 1.7593x; 1.0225x over previous
#include <cuda_runtime.h>
#include <cuda_fp16.h>
#include <math.h>

// ---------------- problem constants ----------------
#define BB   2
#define SS   1024
#define TT   1024
#define HH   2048
#define NHH  16
#define HDD  128
#define MTOK 2048

// ---------------- device scratch ----------------
__device__ float g_ln  [2048u * 1024];   // half: ln out [2048][2048]
__device__ float g_qkv [2048u * 3072];   // half: qkv [2048][6144]
__device__ float g_ctx [2048u * 1024];   // half: ctx [2048][2048]
__device__ float g_x   [2048u * 2048];   // float residual stream
__device__ float g_q   [2048u * 1024];   // half: q [2048][2048]
__device__ float g_kv  [2048u * 2048];   // half: kv [2048][4096]
__device__ float g_mlp [2048u * 4096];   // half: mlp [2048][8192]
__device__ float g_enc [2048u * 1024];   // half: enc [2048][2048]
__device__ float g_vt  [2048u * 2048];   // half: V^T [32][128][1024]
__device__ float g_w   [40u * 1024 * 1024]; // u32: packed half weights

// ---------------- helpers ----------------
__device__ __forceinline__ unsigned pack2(float x, float y) {
    __half2 h = __floats2half2_rn(x, y);
    return *(unsigned*)&h;
}
__device__ __forceinline__ int aswz(int m, int k) {
    return m * 32 + (((((k) >> 2) ^ (m & 7)) << 2) | (k & 3));
}
__device__ __forceinline__ void mma16816(float* c, const unsigned* a, const unsigned* b) {
    asm volatile(
        "mma.sync.aligned.m16n8k16.row.col.f32.f16.f16.f32 "
        "{%0,%1,%2,%3}, {%4,%5,%6,%7}, {%8,%9}, {%0,%1,%2,%3};"
        : "+f"(c[0]), "+f"(c[1]), "+f"(c[2]), "+f"(c[3])
        : "r"(a[0]), "r"(a[1]), "r"(a[2]), "r"(a[3]), "r"(b[0]), "r"(b[1]));
}
__device__ __forceinline__ float gelu_f(float u) {
    return 0.5f * u * (1.f + tanhf(0.7978845608028654f * u * (1.f + 0.044715f * u * u)));
}

// ---------------- reductions ----------------
__device__ __forceinline__ float blockReduceSum(float v, float* sh) {
    int lane = threadIdx.x & 31, w = threadIdx.x >> 5;
    #pragma unroll
    for (int o = 16; o > 0; o >>= 1) v += __shfl_xor_sync(0xffffffffu, v, o);
    if (lane == 0) sh[w] = v;
    __syncthreads();
    float r = 0.f;
    if (w == 0) {
        r = (lane < (blockDim.x >> 5)) ? sh[lane] : 0.f;
        #pragma unroll
        for (int o = 16; o > 0; o >>= 1) r += __shfl_xor_sync(0xffffffffu, r, o);
        if (lane == 0) sh[0] = r;
    }
    __syncthreads();
    r = sh[0];
    __syncthreads();
    return r;
}

// =========================================================================
// Weight pack (ALL weights, one launch): W[K][N] float -> half frag layout.
// Bh[(k>>4)*N*8 + (n>>2)*32 + (n&3)*8 + tg*2 + r]
// =========================================================================
__global__ void __launch_bounds__(256) packall_kernel(
    const float* __restrict__ s0, const float* __restrict__ s1,
    const float* __restrict__ s2, const float* __restrict__ s3,
    const float* __restrict__ s4, const float* __restrict__ s5,
    const float* __restrict__ s6,
    unsigned* __restrict__ d0, unsigned* __restrict__ d1,
    unsigned* __restrict__ d2, unsigned* __restrict__ d3,
    unsigned* __restrict__ d4, unsigned* __restrict__ d5,
    unsigned* __restrict__ d6) {
    // jobs: {K, N}: qkv(2048,6144) ao(2048,2048) q(2048,2048) kv(2048,4096)
    //        co(2048,2048) w1(2048,8192) w2(8192,2048)
    // counts = (K>>4)*(N>>2): 196608,65536,65536,131072,65536,262144,262144
    const int TOTAL = 1048576;
    for (int idx = blockIdx.x * blockDim.x + threadIdx.x; idx < TOTAL;
         idx += gridDim.x * blockDim.x) {
        const float* src; unsigned* dst; int N, local;
        if (idx < 196608)      { src = s0; dst = d0; N = 6144; local = idx; }
        else if (idx < 262144) { src = s1; dst = d1; N = 2048; local = idx - 196608; }
        else if (idx < 327680) { src = s2; dst = d2; N = 2048; local = idx - 262144; }
        else if (idx < 458752) { src = s3; dst = d3; N = 4096; local = idx - 327680; }
        else if (idx < 524288) { src = s4; dst = d4; N = 2048; local = idx - 458752; }
        else if (idx < 786432) { src = s5; dst = d5; N = 8192; local = idx - 524288; }
        else                   { src = s6; dst = d6; N = 2048; local = idx - 786432; }
        int nq = N >> 2;
        int kb = local / nq;
        int n0 = (local - kb * nq) << 2;
        const float* sp = src + (size_t)(kb * 16) * N + n0;
        float4 rv[16];
        #pragma unroll
        for (int r = 0; r < 16; r++) rv[r] = *(const float4*)(sp + (size_t)r * N);
        const float* e = (const float*)rv;   // e[k*4 + nn]
        unsigned outw[32];
        #pragma unroll
        for (int nn = 0; nn < 4; nn++)
            #pragma unroll
            for (int tg = 0; tg < 4; tg++) {
                outw[nn * 8 + tg * 2 + 0] = pack2(e[(2 * tg) * 4 + nn],     e[(2 * tg + 1) * 4 + nn]);
                outw[nn * 8 + tg * 2 + 1] = pack2(e[(2 * tg + 8) * 4 + nn], e[(2 * tg + 9) * 4 + nn]);
            }
        uint4* d = (uint4*)(dst + (size_t)kb * N * 8 + (size_t)(n0 >> 2) * 32);
        #pragma unroll
        for (int i = 0; i < 8; i++) d[i] = ((uint4*)outw)[i];
    }
}

// ---------------- float -> half row-major (encoder states) ----------------
__global__ void __launch_bounds__(256) f2h_kernel(const float2* __restrict__ src,
                                                  unsigned* __restrict__ dst, int n2) {
    for (int i = blockIdx.x * blockDim.x + threadIdx.x; i < n2;
         i += gridDim.x * blockDim.x) {
        float2 v = src[i];
        dst[i] = pack2(v.x, v.y);
    }
}

// ---------------- layernorm: float in -> half row-major out ----------------
__global__ void __launch_bounds__(256) ln_kernel(const float* __restrict__ x,
                                                 const float* __restrict__ gw,
                                                 const float* __restrict__ gb,
                                                 __half* __restrict__ out) {
    __shared__ float sh[32];
    size_t base = (size_t)blockIdx.x * HH;
    int tid = threadIdx.x;
    float4 a = *(const float4*)(x + base + tid * 4);
    float4 b = *(const float4*)(x + base + 1024 + tid * 4);
    float s = a.x + a.y + a.z + a.w + b.x + b.y + b.z + b.w;
    s = blockReduceSum(s, sh);
    float mean = s * (1.f / HH);
    float d, sq = 0.f;
    d = a.x - mean; sq += d * d; d = a.y - mean; sq += d * d;
    d = a.z - mean; sq += d * d; d = a.w - mean; sq += d * d;
    d = b.x - mean; sq += d * d; d = b.y - mean; sq += d * d;
    d = b.z - mean; sq += d * d; d = b.w - mean; sq += d * d;
    sq = blockReduceSum(sq, sh);
    float rstd = rsqrtf(sq * (1.f / HH) + 1e-5f);
    float4 g0 = *(const float4*)(gw + tid * 4);
    float4 g1 = *(const float4*)(gw + 1024 + tid * 4);
    float4 b0 = *(const float4*)(gb + tid * 4);
    float4 b1 = *(const float4*)(gb + 1024 + tid * 4);
    uint2 o0, o1;
    o0.x = pack2((a.x - mean) * rstd * g0.x + b0.x, (a.y - mean) * rstd * g0.y + b0.y);
    o0.y = pack2((a.z - mean) * rstd * g0.z + b0.z, (a.w - mean) * rstd * g0.w + b0.w);
    o1.x = pack2((b.x - mean) * rstd * g1.x + b1.x, (b.y - mean) * rstd * g1.y + b1.y);
    o1.y = pack2((b.z - mean) * rstd * g1.z + b1.z, (b.w - mean) * rstd * g1.w + b1.w);
    *(uint2*)(out + base + tid * 4)        = o0;
    *(uint2*)(out + base + 1024 + tid * 4) = o1;
}

// ---------------- V transpose ----------------
__global__ void __launch_bounds__(256) vtrans_kernel(const __half* __restrict__ src, int lds,
                                                     __half* __restrict__ dst) {
    __shared__ __half t[32][33];
    int z = blockIdx.z;
    int bb = z >> 4, h = z & 15;
    int t0 = blockIdx.x * 32, d0 = blockIdx.y * 32;
    int tx = threadIdx.x & 31, ty = threadIdx.x >> 5;   // 32 x 8
    const __half* s = src + (size_t)(bb * SS + t0 + ty) * lds + h * HDD + d0 + tx;
    #pragma unroll
    for (int r = 0; r < 4; r++)
        t[ty + 8 * r][tx] = s[(size_t)(8 * r) * lds];
    __syncthreads();
    __half* d = dst + (size_t)z * HDD * SS + (size_t)(d0 + ty) * SS + t0 + tx;
    #pragma unroll
    for (int r = 0; r < 4; r++)
        d[(size_t)(8 * r) * SS] = t[tx][ty + 8 * r];
}

// =========================================================================
// FP16 GEMM body (device). A half row-major, B packed. Block 128x128,
// BK=64 halves, 3-stage cp.async, 256 thr, warp 32x64. Smem 96KB.
// =========================================================================
#define GEMM_SMEM (3 * (16384 + 16384))

template<int DO_GELU, int DO_RES, int OUT_HALF>
__device__ __forceinline__ void gemm_body(
    unsigned* smu, int m0, int n0,
    const __half* __restrict__ Ap, int lda,
    const unsigned* __restrict__ Bp, int N,
    const float* __restrict__ bias,
    const float* __restrict__ res,
    void* __restrict__ Cv, int ldc, int K) {
    unsigned* As = smu;             // 3 x 4096 u32
    unsigned* Bs = smu + 12288;     // 3 x 4096 u32
    const int tid = threadIdx.x;
    const int NC = K >> 6;

    const int arow = tid >> 1;
    unsigned a_base = (unsigned)__cvta_generic_to_shared(As) + arow * 128;
    unsigned b_base = (unsigned)__cvta_generic_to_shared(Bs) + tid * 16;
    unsigned a_off[4];
    #pragma unroll
    for (int i = 0; i < 4; i++) {
        int j = (tid & 1) * 4 + i;
        a_off[i] = ((j ^ (arow & 7)) * 16);
    }
    const __half* Asrc = Ap + (size_t)(m0 + arow) * lda + (tid & 1) * 32;
    const unsigned* Bsrc = Bp + (size_t)n0 * 8 + tid * 4;
    const size_t bk16 = (size_t)N * 8;

    #define GISSUE(c) do {                                                        \
        int st_ = (c) % 3;                                                        \
        const __half* ap_ = Asrc + (c) * 64;                                      \
        _Pragma("unroll")                                                         \
        for (int i_ = 0; i_ < 4; i_++) {                                          \
            asm volatile("cp.async.ca.shared.global [%0],[%1],16;" ::             \
                "r"(a_base + st_ * 16384 + a_off[i_]), "l"(ap_ + i_ * 8));        \
            asm volatile("cp.async.ca.shared.global [%0],[%1],16;" ::             \
                "r"(b_base + st_ * 16384 + i_ * 4096),                            \
                "l"(Bsrc + (size_t)(4 * (c) + i_) * bk16));                       \
        }                                                                         \
    } while (0)

    GISSUE(0); asm volatile("cp.async.commit_group;");
    GISSUE(1); asm volatile("cp.async.commit_group;");

    const int lane = tid & 31, wid = tid >> 5;
    const int g = lane >> 2, tg = lane & 3;
    const int wm = (wid & 3) * 32, wn = (wid >> 2) * 64;
    const int nbase = wn * 8 + (g >> 2) * 32 + (g & 3) * 8 + 2 * tg;
    float acc[2][8][4] = {};

    for (int c = 0; c < NC; c++) {
        if (c + 2 < NC) GISSUE(c + 2);
        asm volatile("cp.async.commit_group;");
        asm volatile("cp.async.wait_group 2;");
        __syncthreads();
        const unsigned* Ast = As + (c % 3) * 4096;
        const unsigned* Bst = Bs + (c % 3) * 4096;
        #pragma unroll
        for (int kk = 0; kk < 4; kk++) {
            unsigned afr[2][4], bfr[8][2];
            #pragma unroll
            for (int mt = 0; mt < 2; mt++) {
                int m = wm + mt * 16 + g;
                afr[mt][0] = Ast[aswz(m,     8 * kk + tg)];
                afr[mt][1] = Ast[aswz(m + 8, 8 * kk + tg)];
                afr[mt][2] = Ast[aswz(m,     8 * kk + tg + 4)];
                afr[mt][3] = Ast[aswz(m + 8, 8 * kk + tg + 4)];
            }
            #pragma unroll
            for (int j = 0; j < 8; j++) {
                uint2 bv = *(const uint2*)(Bst + kk * 1024 + nbase + j * 64);
                bfr[j][0] = bv.x; bfr[j][1] = bv.y;
            }
            #pragma unroll
            for (int mt = 0; mt < 2; mt++)
                #pragma unroll
                for (int j = 0; j < 8; j++) mma16816(acc[mt][j], afr[mt], bfr[j]);
        }
        __syncthreads();
    }
    #undef GISSUE

    // epilogue
    #pragma unroll
    for (int mt = 0; mt < 2; mt++) {
        int r = m0 + wm + mt * 16 + g;
        #pragma unroll
        for (int j = 0; j < 8; j++) {
            int cidx = n0 + wn + j * 8 + tg * 2;
            float2 bv = *(const float2*)(bias + cidx);
            float2 v0, v1;
            v0.x = acc[mt][j][0] + bv.x; v0.y = acc[mt][j][1] + bv.y;
            v1.x = acc[mt][j][2] + bv.x; v1.y = acc[mt][j][3] + bv.y;
            if (DO_GELU) {
                v0.x = gelu_f(v0.x); v0.y = gelu_f(v0.y);
                v1.x = gelu_f(v1.x); v1.y = gelu_f(v1.y);
            }
            if (DO_RES) {
                float2 r0 = *(const float2*)(res + (size_t)r * ldc + cidx);
                float2 r1 = *(const float2*)(res + (size_t)(r + 8) * ldc + cidx);
                v0.x += r0.x; v0.y += r0.y; v1.x += r1.x; v1.y += r1.y;
            }
            if (OUT_HALF) {
                __half* Ch = (__half*)Cv;
                *(unsigned*)(Ch + (size_t)r * ldc + cidx)       = pack2(v0.x, v0.y);
                *(unsigned*)(Ch + (size_t)(r + 8) * ldc + cidx) = pack2(v1.x, v1.y);
            } else {
                float* Cf = (float*)Cv;
                *(float2*)(Cf + (size_t)r * ldc + cidx) = v0;
                *(float2*)(Cf + (size_t)(r + 8) * ldc + cidx) = v1;
            }
        }
    }
}

template<int DO_GELU, int DO_RES, int OUT_HALF>
__global__ void __launch_bounds__(256, 2) tc_gemm(
    const __half* __restrict__ Ap, int lda,
    const unsigned* __restrict__ Bp, int N,
    const float* __restrict__ bias,
    const float* __restrict__ res,
    void* __restrict__ Cv, int ldc, int K) {
    extern __shared__ unsigned smu[];
    gemm_body<DO_GELU, DO_RES, OUT_HALF>(smu, blockIdx.y * 128, blockIdx.x * 128,
                                         Ap, lda, Bp, N, bias, res, Cv, ldc, K);
}

// =========================================================================
// FP16 flash attention body. Q,K half row-major; V pre-transposed.
// smem u32: Q 2x4096 | K 2bufs x 4096 | V 4096 | P 4096 = 96KB
// =========================================================================
#define FLASH_SMEM (24576 * 4)

template<int CAUSAL>
__device__ __forceinline__ void flash_body(
    unsigned* smu, int mb, int z,
    const __half* __restrict__ Q, int ldq,
    const __half* __restrict__ Kg, int ldk,
    const __half* __restrict__ Vt,
    __half* __restrict__ O, int skv, float scale) {
    unsigned* Qu = smu;            // 2 chunks x 4096
    unsigned* Ku = smu + 8192;     // 2 bufs x (2 chunks x 2048)
    unsigned* Vu = smu + 16384;    // 4096
    unsigned* Pu = smu + 20480;    // 4096
    const unsigned q_sb = (unsigned)__cvta_generic_to_shared(Qu);
    const unsigned k_sb = (unsigned)__cvta_generic_to_shared(Ku);
    const unsigned v_sb = (unsigned)__cvta_generic_to_shared(Vu);
    const int tid = threadIdx.x;
    const int lane = tid & 31, wid = tid >> 5;
    const int g = lane >> 2, tg = lane & 3;
    const int bb = z / NHH, h = z % NHH;
    const int m0 = mb * 128;
    const __half* Qb = Q + (size_t)bb * SS * ldq + h * HDD;
    const __half* Kb = Kg + (size_t)bb * skv * ldk + h * HDD;
    const __half* Vb = Vt + (size_t)z * HDD * SS;
    __half* Ob = O + (size_t)bb * SS * HH + h * HDD;

    // ---- load Q (128 x 128 halves) ----
    {
        int row = tid >> 1;
        const __half* src = Qb + (size_t)(m0 + row) * ldq;
        unsigned db = q_sb + row * 128;
        #pragma unroll
        for (int i = 0; i < 8; i++) {
            int jj = (tid & 1) * 8 + i;
            asm volatile("cp.async.ca.shared.global [%0],[%1],16;" ::
                "r"(db + (jj >> 3) * 16384 + (((jj & 7) ^ (row & 7)) * 16)),
                "l"(src + jj * 8));
        }
    }
    asm volatile("cp.async.commit_group;");

    #define ISSUE_K(it, buf) do {                                                  \
        int row_ = tid >> 2;                                                       \
        const __half* sp_ = Kb + (size_t)((it) * 64 + row_) * ldk;                 \
        unsigned db_ = k_sb + (buf) * 16384 + row_ * 128;                          \
        _Pragma("unroll")                                                          \
        for (int i_ = 0; i_ < 4; i_++) {                                           \
            int jj_ = (tid & 3) * 4 + i_;                                          \
            asm volatile("cp.async.ca.shared.global [%0],[%1],16;" ::              \
                "r"(db_ + (jj_ >> 3) * 8192 + (((jj_ & 7) ^ (row_ & 7)) * 16)),    \
                "l"(sp_ + jj_ * 8));                                               \
        }                                                                          \
    } while (0)

    #define ISSUE_V(it) do {                                                       \
        int row_ = tid >> 1;                                                       \
        const __half* sp_ = Vb + (size_t)row_ * SS + (it) * 64;                    \
        unsigned db_ = v_sb + row_ * 128;                                          \
        _Pragma("unroll")                                                          \
        for (int i_ = 0; i_ < 4; i_++) {                                           \
            int jj_ = (tid & 1) * 4 + i_;                                          \
            asm volatile("cp.async.ca.shared.global [%0],[%1],16;" ::              \
                "r"(db_ + ((jj_ ^ (row_ & 7)) * 16)), "l"(sp_ + jj_ * 8));         \
        }                                                                          \
    } while (0)

    ISSUE_K(0, 0);
    asm volatile("cp.async.commit_group;");
    asm volatile("cp.async.wait_group 0;");
    __syncthreads();

    const int nkv = CAUSAL ? (2 * mb + 2) : (skv >> 6);
    float m_r[2] = {-1e30f, -1e30f};
    float l_r[2] = {0.f, 0.f};
    float acc_o[16][4] = {};
    const int mrow = wid * 16 + g;

    for (int it = 0; it < nkv; it++) {
        __syncthreads();   // protect Vu / K-buffer reuse
        ISSUE_V(it);
        asm volatile("cp.async.commit_group;");
        const bool more = (it + 1 < nkv);
        if (more) {
            ISSUE_K(it + 1, (it + 1) & 1);
            asm volatile("cp.async.commit_group;");
        }
        if (more) asm volatile("cp.async.wait_group 2;");
        else      asm volatile("cp.async.wait_group 1;");
        __syncthreads();

        // ---- S = Q K^T (16 x 64 per warp) ----
        float acc_s[8][4] = {};
        #pragma unroll
        for (int cq = 0; cq < 2; cq++) {
            const unsigned* Qc = Qu + cq * 4096;
            const unsigned* Kc = Ku + (it & 1) * 4096 + cq * 2048;
            #pragma unroll
            for (int kk = 0; kk < 4; kk++) {
                unsigned afr[4], bfr[8][2];
                afr[0] = Qc[aswz(mrow,     8 * kk + tg)];
                afr[1] = Qc[aswz(mrow + 8, 8 * kk + tg)];
                afr[2] = Qc[aswz(mrow,     8 * kk + tg + 4)];
                afr[3] = Qc[aswz(mrow + 8, 8 * kk + tg + 4)];
                #pragma unroll
                for (int j = 0; j < 8; j++) {
                    bfr[j][0] = Kc[aswz(j * 8 + g, 8 * kk + tg)];
                    bfr[j][1] = Kc[aswz(j * 8 + g, 8 * kk + tg + 4)];
                }
                #pragma unroll
                for (int j = 0; j < 8; j++) mma16816(acc_s[j], afr, bfr[j]);
            }
        }

        // ---- scale + causal mask ----
        const bool diag = CAUSAL && (it >= 2 * mb);
        #pragma unroll
        for (int j = 0; j < 8; j++)
            #pragma unroll
            for (int e = 0; e < 4; e++) {
                float s = acc_s[j][e] * scale;
                if (diag) {
                    int col = it * 64 + j * 8 + tg * 2 + (e & 1);
                    int row = m0 + mrow + (e >> 1) * 8;
                    if (col > row) s = -1e30f;
                }
                acc_s[j][e] = s;
            }

        // ---- online softmax ----
        #pragma unroll
        for (int half = 0; half < 2; half++) {
            float bm = -1e30f;
            #pragma unroll
            for (int j = 0; j < 8; j++)
                bm = fmaxf(bm, fmaxf(acc_s[j][half * 2], acc_s[j][half * 2 + 1]));
            bm = fmaxf(bm, __shfl_xor_sync(0xffffffffu, bm, 1));
            bm = fmaxf(bm, __shfl_xor_sync(0xffffffffu, bm, 2));
            float mnew = fmaxf(m_r[half], bm);
            float alpha = __expf(m_r[half] - mnew);
            float sum = 0.f;
            #pragma unroll
            for (int j = 0; j < 8; j++) {
                float p0 = __expf(acc_s[j][half * 2]     - mnew);
                float p1 = __expf(acc_s[j][half * 2 + 1] - mnew);
                acc_s[j][half * 2]     = p0;
                acc_s[j][half * 2 + 1] = p1;
                sum += p0 + p1;
            }
            sum += __shfl_xor_sync(0xffffffffu, sum, 1);
            sum += __shfl_xor_sync(0xffffffffu, sum, 2);
            l_r[half] = l_r[half] * alpha + sum;
            m_r[half] = mnew;
            #pragma unroll
            for (int j = 0; j < 16; j++) {
                acc_o[j][half * 2]     *= alpha;
                acc_o[j][half * 2 + 1] *= alpha;
            }
        }

        // ---- store P (half) to swizzled smem ----
        #pragma unroll
        for (int half = 0; half < 2; half++) {
            int row = mrow + half * 8;
            #pragma unroll
            for (int j = 0; j < 8; j++)
                Pu[aswz(row, j * 4 + tg)] =
                    pack2(acc_s[j][half * 2], acc_s[j][half * 2 + 1]);
        }
        __syncwarp();

        if (more) asm volatile("cp.async.wait_group 1;");
        else      asm volatile("cp.async.wait_group 0;");
        __syncthreads();

        // ---- O += P V  (16 x 128 per warp) ----
        #pragma unroll
        for (int kk = 0; kk < 4; kk++) {
            unsigned afr[4], bfr[16][2];
            afr[0] = Pu[aswz(mrow,     8 * kk + tg)];
            afr[1] = Pu[aswz(mrow + 8, 8 * kk + tg)];
            afr[2] = Pu[aswz(mrow,     8 * kk + tg + 4)];
            afr[3] = Pu[aswz(mrow + 8, 8 * kk + tg + 4)];
            #pragma unroll
            for (int j = 0; j < 16; j++) {
                bfr[j][0] = Vu[aswz(j * 8 + g, 8 * kk + tg)];
                bfr[j][1] = Vu[aswz(j * 8 + g, 8 * kk + tg + 4)];
            }
            #pragma unroll
            for (int j = 0; j < 16; j++) mma16816(acc_o[j], afr, bfr[j]);
        }
    }
    #undef ISSUE_K
    #undef ISSUE_V

    // ---- epilogue: O /= l, write ctx half ----
    float inv[2] = {1.f / l_r[0], 1.f / l_r[1]};
    #pragma unroll
    for (int half = 0; half < 2; half++) {
        int r = m0 + mrow + half * 8;
        #pragma unroll
        for (int j = 0; j < 16; j++) {
            int col = j * 8 + tg * 2;
            *(unsigned*)(Ob + (size_t)r * HH + col) =
                pack2(acc_o[j][half * 2] * inv[half], acc_o[j][half * 2 + 1] * inv[half]);
        }
    }
}

template<int CAUSAL>
__global__ void __launch_bounds__(256) flash_kernel(
    const __half* __restrict__ Q, int ldq,
    const __half* __restrict__ Kg, int ldk,
    const __half* __restrict__ Vt,
    __half* __restrict__ O, int skv, float scale) {
    extern __shared__ unsigned smu[];
    flash_body<CAUSAL>(smu, blockIdx.x, blockIdx.y, Q, ldq, Kg, ldk, Vt, O, skv, scale);
}

// =========================================================================
// Fused: self-attn flash (grid y<32) + kv projection GEMM backfill (y>=32)
// =========================================================================
__global__ void __launch_bounds__(256, 2) fused_flash_kv(
    const __half* __restrict__ Q, const __half* __restrict__ Kg,
    const __half* __restrict__ Vt, __half* __restrict__ Octx,
    const __half* __restrict__ Aenc, const unsigned* __restrict__ Bkv,
    const float* __restrict__ bkv, __half* __restrict__ Ckv, float scale) {
    extern __shared__ unsigned smu[];
    if (blockIdx.y < 32) {
        flash_body<1>(smu, blockIdx.x, blockIdx.y, Q, 6144, Kg, 6144, Vt, Octx, SS, scale);
    } else {
        int id = (blockIdx.y - 32) * 8 + blockIdx.x;   // 0..511
        gemm_body<0, 0, 1>(smu, (id >> 5) * 128, (id & 31) * 128,
                           Aenc, HH, Bkv, 4096, bkv, nullptr, (void*)Ckv, 4096, HH);
    }
}

// ---------------- host orchestration ----------------
extern "C" void kernel_launch(void* const* d_in, const int* in_sizes, int n_in,
                              void* d_out, int out_size) {
    const float* hs    = (const float*)d_in[0];
    const float* enc   = (const float*)d_in[1];
    // d_in[2] = ltor (tril, structural), d_in[3] = cross mask (ones)
    const float* ln1_s = (const float*)d_in[4];
    const float* ln1_b = (const float*)d_in[5];
    const float* w_qkv = (const float*)d_in[6];
    const float* b_qkv = (const float*)d_in[7];
    const float* w_ao  = (const float*)d_in[8];
    const float* b_ao  = (const float*)d_in[9];
    const float* ln2_s = (const float*)d_in[10];
    const float* ln2_b = (const float*)d_in[11];
    const float* w_q   = (const float*)d_in[12];
    const float* b_q   = (const float*)d_in[13];
    const float* w_kv  = (const float*)d_in[14];
    const float* b_kv  = (const float*)d_in[15];
    const float* w_co  = (const float*)d_in[16];
    const float* b_co  = (const float*)d_in[17];
    const float* ln3_s = (const float*)d_in[18];
    const float* ln3_b = (const float*)d_in[19];
    const float* w1    = (const float*)d_in[20];
    const float* b1    = (const float*)d_in[21];
    const float* w2    = (const float*)d_in[22];
    const float* b2    = (const float*)d_in[23];
    float* out = (float*)d_out;

    void *lnp, *qkvp, *ctxp, *xp, *qp, *kvp, *mlpp, *encp, *vtp, *wp;
    cudaGetSymbolAddress(&lnp,  g_ln);
    cudaGetSymbolAddress(&qkvp, g_qkv);
    cudaGetSymbolAddress(&ctxp, g_ctx);
    cudaGetSymbolAddress(&xp,   g_x);
    cudaGetSymbolAddress(&qp,   g_q);
    cudaGetSymbolAddress(&kvp,  g_kv);
    cudaGetSymbolAddress(&mlpp, g_mlp);
    cudaGetSymbolAddress(&encp, g_enc);
    cudaGetSymbolAddress(&vtp,  g_vt);
    cudaGetSymbolAddress(&wp,   g_w);

    __half* lnh  = (__half*)lnp;
    __half* qkvh = (__half*)qkvp;
    __half* ctxh = (__half*)ctxp;
    float*  x    = (float*)xp;
    __half* qbh  = (__half*)qp;
    __half* kvbh = (__half*)kvp;
    __half* mlph = (__half*)mlpp;
    __half* ench = (__half*)encp;
    __half* vth  = (__half*)vtp;
    unsigned* wh = (unsigned*)wp;

    unsigned* wr_qkv = wh;
    unsigned* wr_ao  = wr_qkv + 2048u * 3072;
    unsigned* wr_q   = wr_ao  + 2048u * 1024;
    unsigned* wr_kv  = wr_q   + 2048u * 1024;
    unsigned* wr_co  = wr_kv  + 2048u * 2048;
    unsigned* wr_w1  = wr_co  + 2048u * 1024;
    unsigned* wr_w2  = wr_w1  + 2048u * 4096;

    cudaFuncSetAttribute(tc_gemm<0, 0, 1>, cudaFuncAttributeMaxDynamicSharedMemorySize, GEMM_SMEM);
    cudaFuncSetAttribute(tc_gemm<0, 1, 0>, cudaFuncAttributeMaxDynamicSharedMemorySize, GEMM_SMEM);
    cudaFuncSetAttribute(tc_gemm<1, 0, 1>, cudaFuncAttributeMaxDynamicSharedMemorySize, GEMM_SMEM);
    cudaFuncSetAttribute(flash_kernel<0>, cudaFuncAttributeMaxDynamicSharedMemorySize, FLASH_SMEM);
    cudaFuncSetAttribute(fused_flash_kv, cudaFuncAttributeMaxDynamicSharedMemorySize, GEMM_SMEM);

    const float scale = 0.08838834764831845f;  // 1/sqrt(128)
    dim3 thr(256);
    dim3 tgrid(32, 4, 32);

    // ---- prep: pack all weights (1 launch), convert encoder ----
    packall_kernel<<<2048, thr>>>(w_qkv, w_ao, w_q, w_kv, w_co, w1, w2,
                                  wr_qkv, wr_ao, wr_q, wr_kv, wr_co, wr_w1, wr_w2);
    f2h_kernel<<<1184, thr>>>((const float2*)enc, (unsigned*)ench, 2048 * 1024);

    // ---- self attention block (+ kv projection backfill) ----
    ln_kernel<<<MTOK, thr>>>(hs, ln1_s, ln1_b, lnh);
    tc_gemm<0, 0, 1><<<dim3(48, 16), thr, GEMM_SMEM>>>(lnh, HH, wr_qkv, 6144, b_qkv, nullptr, qkvh, 6144, HH);
    vtrans_kernel<<<tgrid, thr>>>(qkvh + 4096, 6144, vth);
    fused_flash_kv<<<dim3(8, 96), thr, GEMM_SMEM>>>(qkvh, qkvh + 2048, vth, ctxh,
                                                    ench, wr_kv, b_kv, kvbh, scale);
    tc_gemm<0, 1, 0><<<dim3(16, 16), thr, GEMM_SMEM>>>(ctxh, HH, wr_ao, 2048, b_ao, hs, x, HH, HH);

    // ---- cross attention block ----
    ln_kernel<<<MTOK, thr>>>(x, ln2_s, ln2_b, lnh);
    tc_gemm<0, 0, 1><<<dim3(16, 16), thr, GEMM_SMEM>>>(lnh, HH, wr_q, 2048, b_q, nullptr, qbh, HH, HH);
    vtrans_kernel<<<tgrid, thr>>>(kvbh + 2048, 4096, vth);
    flash_kernel<0><<<dim3(8, 32), thr, FLASH_SMEM>>>(qbh, HH, kvbh, 4096, vth, ctxh, TT, scale);
    tc_gemm<0, 1, 0><<<dim3(16, 16), thr, GEMM_SMEM>>>(ctxh, HH, wr_co, 2048, b_co, x, x, HH, HH);

    // ---- mlp block ----
    ln_kernel<<<MTOK, thr>>>(x, ln3_s, ln3_b, lnh);
    tc_gemm<1, 0, 1><<<dim3(64, 16), thr, GEMM_SMEM>>>(lnh, HH, wr_w1, 8192, b1, nullptr, mlph, 8192, HH);
    tc_gemm<0, 1, 0><<<dim3(16, 16), thr, GEMM_SMEM>>>(mlph, 8192, wr_w2, 2048, b2, x, out, HH, 8192);
}